// round 3
// baseline (speedup 1.0000x reference)
#include <cuda_runtime.h>
#include <cuda_bf16.h>

#define NN 100000
#define EE 1600000
#define HID 128
#define FIN 100
#define CLS 47

typedef unsigned long long ull;

// ---------------- device scratch (no allocs allowed) ----------------
__device__ int   g_deg[NN];
__device__ int   g_rowstart[NN];
__device__ int   g_pos[NN];
__device__ int   g_bsums[128];
__device__ ull   g_perm[EE];          // packed: low32 = src, high32 = w bits
__device__ float g_agg0[(size_t)NN * FIN];
__device__ float g_agg [(size_t)NN * HID];
__device__ float g_x1  [(size_t)NN * HID];
__device__ float g_x2  [(size_t)NN * HID];
__device__ float g_x3  [(size_t)NN * HID];

__device__ __forceinline__ void fma2(ull &acc, ull a, ull b) {
    asm("fma.rn.f32x2 %0, %1, %2, %0;" : "+l"(acc) : "l"(a), "l"(b));
}
__device__ __forceinline__ ull pk(float x, float y) {
    ull r; asm("mov.b64 %0, {%1, %2};" : "=l"(r) : "f"(x), "f"(y)); return r;
}

// ---------------- CSR build ----------------
__global__ void k_zero_deg() {
    int i = blockIdx.x * 256 + threadIdx.x;
    if (i < NN) g_deg[i] = 0;
}

__global__ void k_count(const int* __restrict__ dst) {
    int e = blockIdx.x * 512 + threadIdx.x;
    if (e < EE) atomicAdd(&g_deg[dst[e]], 1);
}

__global__ void k_scanA() {
    __shared__ int s[1024];
    int tid = threadIdx.x;
    int i = blockIdx.x * 1024 + tid;
    int v = (i < NN) ? g_deg[i] : 0;
    s[tid] = v;
    __syncthreads();
    for (int off = 1; off < 1024; off <<= 1) {
        int a = s[tid];
        int b = (tid >= off) ? s[tid - off] : 0;
        __syncthreads();
        s[tid] = a + b;
        __syncthreads();
    }
    if (i < NN) g_rowstart[i] = s[tid] - v;
    if (tid == 1023) g_bsums[blockIdx.x] = s[1023];
}

// scanC now also re-scans the (<=128) block sums locally: removes scanB launch
__global__ void k_scanC(int nb) {
    __shared__ int sb[128];
    __shared__ int se[128];
    int t = threadIdx.x;   // 256 threads
    int v = 0;
    if (t < 128) { v = (t < nb) ? g_bsums[t] : 0; sb[t] = v; }
    __syncthreads();
    for (int off = 1; off < 128; off <<= 1) {
        int a = 0, b = 0;
        if (t < 128) { a = sb[t]; b = (t >= off) ? sb[t - off] : 0; }
        __syncthreads();
        if (t < 128) sb[t] = a + b;
        __syncthreads();
    }
    if (t < 128) se[t] = sb[t] - v;   // exclusive
    __syncthreads();
    int i = blockIdx.x * 256 + t;
    if (i < NN) {
        int r = g_rowstart[i] + se[i >> 10];
        g_rowstart[i] = r;
        g_pos[i] = r;
    }
}

__global__ void k_fill(const int* __restrict__ src, const int* __restrict__ dst,
                       const float* __restrict__ w) {
    int e = blockIdx.x * 512 + threadIdx.x;
    if (e >= EE) return;
    int d = dst[e];
    int p = atomicAdd(&g_pos[d], 1);
    g_perm[p] = ((ull)__float_as_uint(w[e]) << 32) | (unsigned)src[e];
}

// ---------------- aggregation: warp per node, strip-mined x4 ----------------
template <int D>
__global__ __launch_bounds__(256) void k_aggregate(
    const float* __restrict__ x, float* __restrict__ agg)
{
    int gt = blockIdx.x * blockDim.x + threadIdx.x;
    int node = gt >> 5;
    int lane = gt & 31;
    if (node >= NN) return;
    int start = g_rowstart[node];
    int cnt = g_deg[node];
    constexpr int NV = D / 4;
    bool act = lane < NV;
    float4 acc = make_float4(0.f, 0.f, 0.f, 0.f);
    int i = 0;
    for (; i + 4 <= cnt; i += 4) {
        ull e0 = __ldg(&g_perm[start + i + 0]);
        ull e1 = __ldg(&g_perm[start + i + 1]);
        ull e2 = __ldg(&g_perm[start + i + 2]);
        ull e3 = __ldg(&g_perm[start + i + 3]);
        int s0 = (int)(unsigned)e0, s1 = (int)(unsigned)e1;
        int s2 = (int)(unsigned)e2, s3 = (int)(unsigned)e3;
        float w0 = __uint_as_float((unsigned)(e0 >> 32));
        float w1 = __uint_as_float((unsigned)(e1 >> 32));
        float w2 = __uint_as_float((unsigned)(e2 >> 32));
        float w3 = __uint_as_float((unsigned)(e3 >> 32));
        if (act) {
            float4 v0 = __ldg(reinterpret_cast<const float4*>(x + (size_t)s0 * D) + lane);
            float4 v1 = __ldg(reinterpret_cast<const float4*>(x + (size_t)s1 * D) + lane);
            float4 v2 = __ldg(reinterpret_cast<const float4*>(x + (size_t)s2 * D) + lane);
            float4 v3 = __ldg(reinterpret_cast<const float4*>(x + (size_t)s3 * D) + lane);
            acc.x += v0.x * w0 + v1.x * w1 + v2.x * w2 + v3.x * w3;
            acc.y += v0.y * w0 + v1.y * w1 + v2.y * w2 + v3.y * w3;
            acc.z += v0.z * w0 + v1.z * w1 + v2.z * w2 + v3.z * w3;
            acc.w += v0.w * w0 + v1.w * w1 + v2.w * w2 + v3.w * w3;
        }
    }
    for (; i < cnt; i++) {
        ull e = __ldg(&g_perm[start + i]);
        int s = (int)(unsigned)e;
        float wv = __uint_as_float((unsigned)(e >> 32));
        if (act) {
            float4 v = __ldg(reinterpret_cast<const float4*>(x + (size_t)s * D) + lane);
            acc.x += v.x * wv; acc.y += v.y * wv; acc.z += v.z * wv; acc.w += v.w * wv;
        }
    }
    if (act) reinterpret_cast<float4*>(agg + (size_t)node * D)[lane] = acc;
}

// ---------------- fused dual GEMM + bias + relu (f32x2, float4 smem) --------
template <int K>
__global__ __launch_bounds__(256, 1) void k_gemm_dual(
    const float* __restrict__ A, const float* __restrict__ X,
    const float* __restrict__ Wrel, const float* __restrict__ Wroot,
    const float* __restrict__ bias, float* __restrict__ out)
{
    constexpr int K4 = K / 4;
    constexpr int Kpad = K + 4;
    extern __shared__ __align__(16) float sm[];
    float4* Wr4 = (float4*)sm;                 // [K4][129]
    float4* Wt4 = Wr4 + K4 * 129;              // [K4][129]
    float* Aagg = (float*)(Wt4 + K4 * 129);    // [64][Kpad]
    float* Ax   = Aagg + 64 * Kpad;            // [64][Kpad]
    float* bs   = Ax + 64 * Kpad;              // [128]

    int t = threadIdx.x;
    int row0 = blockIdx.x * 64;

    for (int s = t; s < 128 * K4; s += 256) {
        int c = s / K4;
        int k4 = s - c * K4;
        Wr4[k4 * 129 + c] = *(const float4*)(Wrel + c * K + 4 * k4);
        Wt4[k4 * 129 + c] = *(const float4*)(Wroot + c * K + 4 * k4);
    }
    for (int s = t; s < 64 * K4; s += 256) {
        int r = s / K4;
        int k4 = s - r * K4;
        int row = row0 + r;
        float4 va = make_float4(0.f, 0.f, 0.f, 0.f);
        float4 vx = va;
        if (row < NN) {
            va = *(const float4*)(A + (size_t)row * K + 4 * k4);
            vx = *(const float4*)(X + (size_t)row * K + 4 * k4);
        }
        *(float4*)(Aagg + r * Kpad + 4 * k4) = va;
        *(float4*)(Ax   + r * Kpad + 4 * k4) = vx;
    }
    if (t < 128) bs[t] = bias[t];
    __syncthreads();

    int tc = t & 31;
    int tr = t >> 5;
    ull acc[8][4];
#pragma unroll
    for (int i = 0; i < 8; i++)
#pragma unroll
        for (int j = 0; j < 4; j++) acc[i][j] = 0ull;

    const float* Ar = Aagg + (tr * 8) * Kpad;
    const float* Xr = Ax + (tr * 8) * Kpad;

#pragma unroll 2
    for (int k4 = 0; k4 < K4; k4++) {
        ull wRl[4], wRh[4], wTl[4], wTh[4];
#pragma unroll
        for (int j = 0; j < 4; j++) {
            float4 w = Wr4[k4 * 129 + tc + 32 * j];
            wRl[j] = pk(w.x, w.y); wRh[j] = pk(w.z, w.w);
            float4 v = Wt4[k4 * 129 + tc + 32 * j];
            wTl[j] = pk(v.x, v.y); wTh[j] = pk(v.z, v.w);
        }
#pragma unroll
        for (int i = 0; i < 8; i++) {
            float4 a4 = *(const float4*)(Ar + i * Kpad + 4 * k4);
            float4 x4 = *(const float4*)(Xr + i * Kpad + 4 * k4);
            ull al = pk(a4.x, a4.y), ah = pk(a4.z, a4.w);
            ull xl = pk(x4.x, x4.y), xh = pk(x4.z, x4.w);
#pragma unroll
            for (int j = 0; j < 4; j++) {
                fma2(acc[i][j], al, wRl[j]);
                fma2(acc[i][j], ah, wRh[j]);
                fma2(acc[i][j], xl, wTl[j]);
                fma2(acc[i][j], xh, wTh[j]);
            }
        }
    }

#pragma unroll
    for (int i = 0; i < 8; i++) {
        int row = row0 + tr * 8 + i;
        if (row >= NN) continue;
#pragma unroll
        for (int j = 0; j < 4; j++) {
            int c = tc + 32 * j;
            float lo = __uint_as_float((unsigned)acc[i][j]);
            float hi = __uint_as_float((unsigned)(acc[i][j] >> 32));
            float v = lo + hi + bs[c];
            out[(size_t)row * HID + c] = fmaxf(v, 0.f);
        }
    }
}

// ---------------- head GEMM: 64 nodes x 64 cols (47 used), K=384 ------------
__global__ __launch_bounds__(256, 1) void k_head(
    const float* __restrict__ Wlin, const float* __restrict__ blin,
    float* __restrict__ out)
{
    constexpr int K = 384, K4 = 96, Kpad = 388;
    extern __shared__ __align__(16) float sm[];
    float4* W4 = (float4*)sm;              // [K4][65]
    float* Xs = (float*)(W4 + K4 * 65);    // [64][Kpad]
    float* bs = Xs + 64 * Kpad;            // [64]

    int t = threadIdx.x;
    int row0 = blockIdx.x * 64;

    for (int s = t; s < 64 * K4; s += 256) {
        int c = s / K4;
        int k4 = s - c * K4;
        float4 v = make_float4(0.f, 0.f, 0.f, 0.f);
        if (c < CLS) v = *(const float4*)(Wlin + c * K + 4 * k4);
        W4[k4 * 65 + c] = v;
    }
    for (int s = t; s < 64 * K4; s += 256) {
        int r = s / K4;
        int k4 = s - r * K4;
        int row = row0 + r;
        float4 v = make_float4(0.f, 0.f, 0.f, 0.f);
        if (row < NN) {
            if (k4 < 32)      v = *(const float4*)(g_x1 + (size_t)row * HID + 4 * k4);
            else if (k4 < 64) v = *(const float4*)(g_x2 + (size_t)row * HID + 4 * (k4 - 32));
            else              v = *(const float4*)(g_x3 + (size_t)row * HID + 4 * (k4 - 64));
        }
        *(float4*)(Xs + r * Kpad + 4 * k4) = v;
    }
    if (t < 64) bs[t] = (t < CLS) ? blin[t] : 0.f;
    __syncthreads();

    int tc = t & 31;
    int tr = t >> 5;
    ull acc[8][2];
#pragma unroll
    for (int i = 0; i < 8; i++) { acc[i][0] = 0ull; acc[i][1] = 0ull; }

    const float* Xr = Xs + (tr * 8) * Kpad;

#pragma unroll 2
    for (int k4 = 0; k4 < K4; k4++) {
        ull wl[2], wh[2];
#pragma unroll
        for (int j = 0; j < 2; j++) {
            float4 w = W4[k4 * 65 + tc + 32 * j];
            wl[j] = pk(w.x, w.y); wh[j] = pk(w.z, w.w);
        }
#pragma unroll
        for (int i = 0; i < 8; i++) {
            float4 a4 = *(const float4*)(Xr + i * Kpad + 4 * k4);
            ull al = pk(a4.x, a4.y), ah = pk(a4.z, a4.w);
#pragma unroll
            for (int j = 0; j < 2; j++) {
                fma2(acc[i][j], al, wl[j]);
                fma2(acc[i][j], ah, wh[j]);
            }
        }
    }

    bool valid1 = (tc + 32) < CLS;
#pragma unroll
    for (int i = 0; i < 8; i++) {
        int row = row0 + tr * 8 + i;
        float v0 = __uint_as_float((unsigned)acc[i][0]) +
                   __uint_as_float((unsigned)(acc[i][0] >> 32)) + bs[tc];
        float v1 = __uint_as_float((unsigned)acc[i][1]) +
                   __uint_as_float((unsigned)(acc[i][1] >> 32)) + bs[tc + 32];
        float m = valid1 ? fmaxf(v0, v1) : v0;
#pragma unroll
        for (int o = 16; o > 0; o >>= 1) m = fmaxf(m, __shfl_xor_sync(0xffffffffu, m, o));
        float se = expf(v0 - m) + (valid1 ? expf(v1 - m) : 0.f);
#pragma unroll
        for (int o = 16; o > 0; o >>= 1) se += __shfl_xor_sync(0xffffffffu, se, o);
        float lse = m + logf(se);
        if (row < NN) {
            out[(size_t)row * CLS + tc] = v0 - lse;
            if (valid1) out[(size_t)row * CLS + tc + 32] = v1 - lse;
        }
    }
}

// ---------------- launch ----------------
extern "C" void kernel_launch(void* const* d_in, const int* in_sizes, int n_in,
                              void* d_out, int out_size)
{
    const float* x0    = (const float*)d_in[0];
    const int*   ei    = (const int*)  d_in[1];
    const float* ew    = (const float*)d_in[2];
    const float* W1rel = (const float*)d_in[3];
    const float* W1rt  = (const float*)d_in[4];
    const float* b1    = (const float*)d_in[5];
    const float* W2rel = (const float*)d_in[6];
    const float* W2rt  = (const float*)d_in[7];
    const float* b2    = (const float*)d_in[8];
    const float* W3rel = (const float*)d_in[9];
    const float* W3rt  = (const float*)d_in[10];
    const float* b3    = (const float*)d_in[11];
    const float* Wlin  = (const float*)d_in[12];
    const float* blin  = (const float*)d_in[13];
    float* out = (float*)d_out;

    const int* src = ei;
    const int* dst = ei + EE;

    float *agg0p, *aggp, *x1p, *x2p, *x3p;
    cudaGetSymbolAddress((void**)&agg0p, g_agg0);
    cudaGetSymbolAddress((void**)&aggp,  g_agg);
    cudaGetSymbolAddress((void**)&x1p,   g_x1);
    cudaGetSymbolAddress((void**)&x2p,   g_x2);
    cudaGetSymbolAddress((void**)&x3p,   g_x3);

    const int smem128 = (2 * 129 * 32) * 16 + (2 * 64 * 132) * 4 + 512;  // 200192
    const int smem100 = (2 * 129 * 25) * 16 + (2 * 64 * 104) * 4 + 512;  // 156960
    const int smemH   = (96 * 65) * 16 + (64 * 388) * 4 + 256;           // 199424
    cudaFuncSetAttribute(k_gemm_dual<128>, cudaFuncAttributeMaxDynamicSharedMemorySize, smem128);
    cudaFuncSetAttribute(k_gemm_dual<100>, cudaFuncAttributeMaxDynamicSharedMemorySize, smem100);
    cudaFuncSetAttribute(k_head,           cudaFuncAttributeMaxDynamicSharedMemorySize, smemH);

    const int NB = (NN + 1023) / 1024;   // 98

    // CSR build (5 launches -> 6th launch is k_aggregate<FIN> for ncu)
    k_zero_deg<<<(NN + 255) / 256, 256>>>();
    k_count<<<(EE + 511) / 512, 512>>>(dst);
    k_scanA<<<NB, 1024>>>();
    k_scanC<<<(NN + 255) / 256, 256>>>(NB);
    k_fill<<<(EE + 511) / 512, 512>>>(src, dst, ew);

    const int aggBlocks = NN * 32 / 256;
    const int gemmBlocks = (NN + 63) / 64;

    // layer 1 (K = 100)
    k_aggregate<FIN><<<aggBlocks, 256>>>(x0, agg0p);
    k_gemm_dual<100><<<gemmBlocks, 256, smem100>>>(agg0p, x0, W1rel, W1rt, b1, x1p);
    // layer 2
    k_aggregate<HID><<<aggBlocks, 256>>>(x1p, aggp);
    k_gemm_dual<128><<<gemmBlocks, 256, smem128>>>(aggp, x1p, W2rel, W2rt, b2, x2p);
    // layer 3
    k_aggregate<HID><<<aggBlocks, 256>>>(x2p, aggp);
    k_gemm_dual<128><<<gemmBlocks, 256, smem128>>>(aggp, x2p, W3rel, W3rt, b3, x3p);
    // head
    k_head<<<(NN + 63) / 64, 256, smemH>>>(Wlin, blin, out);
}

// round 4
// speedup vs baseline: 1.0275x; 1.0275x over previous
#include <cuda_runtime.h>
#include <cuda_fp16.h>
#include <cuda_bf16.h>

#define NN 100000
#define EE 1600000
#define HID 128
#define FIN 100
#define CLS 47

typedef unsigned long long ull;

// ---------------- device scratch (no allocs allowed) ----------------
__device__ int    g_deg[NN];
__device__ int    g_rowstart[NN];   // within-block exclusive (local) offsets
__device__ int    g_pos[NN];
__device__ int    g_bsums[128];     // zero-init; only [0,nb) ever written
__device__ ull    g_perm[EE];       // packed: low32 = src, high32 = w bits
__device__ float  g_agg0[(size_t)NN * FIN];
__device__ float  g_agg [(size_t)NN * HID];
__device__ float  g_x1  [(size_t)NN * HID];
__device__ float  g_x2  [(size_t)NN * HID];
__device__ float  g_x3  [(size_t)NN * HID];
__device__ __half g_h1  [(size_t)NN * HID];
__device__ __half g_h2  [(size_t)NN * HID];

__device__ __forceinline__ void fma2(ull &acc, ull a, ull b) {
    asm("fma.rn.f32x2 %0, %1, %2, %0;" : "+l"(acc) : "l"(a), "l"(b));
}
__device__ __forceinline__ ull pk(float x, float y) {
    ull r; asm("mov.b64 %0, {%1, %2};" : "=l"(r) : "f"(x), "f"(y)); return r;
}

// 128-wide exclusive scan of g_bsums into se[]; call with >=128 threads, all
// threads must participate in barriers.
#define BSUM_SCAN(sb, se)                                            \
    {                                                                \
        int _t = threadIdx.x;                                        \
        if (_t < 128) sb[_t] = g_bsums[_t];                          \
        __syncthreads();                                             \
        for (int off = 1; off < 128; off <<= 1) {                    \
            int _a = 0, _b = 0;                                      \
            if (_t < 128) { _a = sb[_t]; _b = (_t >= off) ? sb[_t - off] : 0; } \
            __syncthreads();                                         \
            if (_t < 128) sb[_t] = _a + _b;                          \
            __syncthreads();                                         \
        }                                                            \
        if (_t < 128) se[_t] = sb[_t] - g_bsums[_t];                 \
        __syncthreads();                                             \
    }

// ---------------- CSR build (3 kernels; g_deg zeroed by memset node) --------
__global__ void k_count(const int* __restrict__ dst) {
    int e = blockIdx.x * 512 + threadIdx.x;
    if (e < EE) atomicAdd(&g_deg[dst[e]], 1);
}

__global__ void k_scanA() {
    __shared__ int s[1024];
    int tid = threadIdx.x;
    int i = blockIdx.x * 1024 + tid;
    int v = (i < NN) ? g_deg[i] : 0;
    s[tid] = v;
    __syncthreads();
    for (int off = 1; off < 1024; off <<= 1) {
        int a = s[tid];
        int b = (tid >= off) ? s[tid - off] : 0;
        __syncthreads();
        s[tid] = a + b;
        __syncthreads();
    }
    if (i < NN) {
        int loc = s[tid] - v;
        g_rowstart[i] = loc;
        g_pos[i] = loc;
    }
    if (tid == 1023) g_bsums[blockIdx.x] = s[1023];
}

__global__ void k_fill(const int* __restrict__ src, const int* __restrict__ dst,
                       const float* __restrict__ w) {
    __shared__ int sb[128];
    __shared__ int se[128];
    BSUM_SCAN(sb, se);
    int e = blockIdx.x * 512 + threadIdx.x;
    if (e >= EE) return;
    int d = dst[e];
    int p = atomicAdd(&g_pos[d], 1) + se[d >> 10];
    g_perm[p] = ((ull)__float_as_uint(w[e]) << 32) | (unsigned)src[e];
}

// ---------------- aggregation (fp32 source), warp per node ------------------
template <int D>
__global__ __launch_bounds__(256) void k_aggregate(
    const float* __restrict__ x, float* __restrict__ agg)
{
    __shared__ int sb[128];
    __shared__ int se[128];
    BSUM_SCAN(sb, se);
    int gt = blockIdx.x * 256 + threadIdx.x;
    int node = gt >> 5;
    int lane = gt & 31;
    if (node >= NN) return;
    int start = g_rowstart[node] + se[node >> 10];
    int cnt = g_deg[node];
    constexpr int NV = D / 4;
    bool act = lane < NV;
    float4 acc = make_float4(0.f, 0.f, 0.f, 0.f);
    int i = 0;
    for (; i + 4 <= cnt; i += 4) {
        ull e0 = __ldg(&g_perm[start + i + 0]);
        ull e1 = __ldg(&g_perm[start + i + 1]);
        ull e2 = __ldg(&g_perm[start + i + 2]);
        ull e3 = __ldg(&g_perm[start + i + 3]);
        int s0 = (int)(unsigned)e0, s1 = (int)(unsigned)e1;
        int s2 = (int)(unsigned)e2, s3 = (int)(unsigned)e3;
        float w0 = __uint_as_float((unsigned)(e0 >> 32));
        float w1 = __uint_as_float((unsigned)(e1 >> 32));
        float w2 = __uint_as_float((unsigned)(e2 >> 32));
        float w3 = __uint_as_float((unsigned)(e3 >> 32));
        if (act) {
            float4 v0 = __ldg(reinterpret_cast<const float4*>(x + (size_t)s0 * D) + lane);
            float4 v1 = __ldg(reinterpret_cast<const float4*>(x + (size_t)s1 * D) + lane);
            float4 v2 = __ldg(reinterpret_cast<const float4*>(x + (size_t)s2 * D) + lane);
            float4 v3 = __ldg(reinterpret_cast<const float4*>(x + (size_t)s3 * D) + lane);
            acc.x += v0.x * w0 + v1.x * w1 + v2.x * w2 + v3.x * w3;
            acc.y += v0.y * w0 + v1.y * w1 + v2.y * w2 + v3.y * w3;
            acc.z += v0.z * w0 + v1.z * w1 + v2.z * w2 + v3.z * w3;
            acc.w += v0.w * w0 + v1.w * w1 + v2.w * w2 + v3.w * w3;
        }
    }
    for (; i < cnt; i++) {
        ull e = __ldg(&g_perm[start + i]);
        int s = (int)(unsigned)e;
        float wv = __uint_as_float((unsigned)(e >> 32));
        if (act) {
            float4 v = __ldg(reinterpret_cast<const float4*>(x + (size_t)s * D) + lane);
            acc.x += v.x * wv; acc.y += v.y * wv; acc.z += v.z * wv; acc.w += v.w * wv;
        }
    }
    if (act) reinterpret_cast<float4*>(agg + (size_t)node * D)[lane] = acc;
}

// ---------------- aggregation (fp16 source, HID=128), warp per node ---------
__global__ __launch_bounds__(256) void k_agg_h(
    const __half* __restrict__ x, float* __restrict__ agg)
{
    __shared__ int sb[128];
    __shared__ int se[128];
    BSUM_SCAN(sb, se);
    int gt = blockIdx.x * 256 + threadIdx.x;
    int node = gt >> 5;
    int lane = gt & 31;
    if (node >= NN) return;
    int start = g_rowstart[node] + se[node >> 10];
    int cnt = g_deg[node];
    float4 acc = make_float4(0.f, 0.f, 0.f, 0.f);
    int i = 0;
    for (; i + 4 <= cnt; i += 4) {
        ull e0 = __ldg(&g_perm[start + i + 0]);
        ull e1 = __ldg(&g_perm[start + i + 1]);
        ull e2 = __ldg(&g_perm[start + i + 2]);
        ull e3 = __ldg(&g_perm[start + i + 3]);
        int s0 = (int)(unsigned)e0, s1 = (int)(unsigned)e1;
        int s2 = (int)(unsigned)e2, s3 = (int)(unsigned)e3;
        float w0 = __uint_as_float((unsigned)(e0 >> 32));
        float w1 = __uint_as_float((unsigned)(e1 >> 32));
        float w2 = __uint_as_float((unsigned)(e2 >> 32));
        float w3 = __uint_as_float((unsigned)(e3 >> 32));
        uint2 v0 = __ldg(reinterpret_cast<const uint2*>(x + (size_t)s0 * HID) + lane);
        uint2 v1 = __ldg(reinterpret_cast<const uint2*>(x + (size_t)s1 * HID) + lane);
        uint2 v2 = __ldg(reinterpret_cast<const uint2*>(x + (size_t)s2 * HID) + lane);
        uint2 v3 = __ldg(reinterpret_cast<const uint2*>(x + (size_t)s3 * HID) + lane);
        float2 a0 = __half22float2(*(__half2*)&v0.x), b0 = __half22float2(*(__half2*)&v0.y);
        float2 a1 = __half22float2(*(__half2*)&v1.x), b1 = __half22float2(*(__half2*)&v1.y);
        float2 a2 = __half22float2(*(__half2*)&v2.x), b2 = __half22float2(*(__half2*)&v2.y);
        float2 a3 = __half22float2(*(__half2*)&v3.x), b3 = __half22float2(*(__half2*)&v3.y);
        acc.x += a0.x * w0 + a1.x * w1 + a2.x * w2 + a3.x * w3;
        acc.y += a0.y * w0 + a1.y * w1 + a2.y * w2 + a3.y * w3;
        acc.z += b0.x * w0 + b1.x * w1 + b2.x * w2 + b3.x * w3;
        acc.w += b0.y * w0 + b1.y * w1 + b2.y * w2 + b3.y * w3;
    }
    for (; i < cnt; i++) {
        ull e = __ldg(&g_perm[start + i]);
        int s = (int)(unsigned)e;
        float wv = __uint_as_float((unsigned)(e >> 32));
        uint2 v = __ldg(reinterpret_cast<const uint2*>(x + (size_t)s * HID) + lane);
        float2 a = __half22float2(*(__half2*)&v.x), b = __half22float2(*(__half2*)&v.y);
        acc.x += a.x * wv; acc.y += a.y * wv; acc.z += b.x * wv; acc.w += b.y * wv;
    }
    // features [4*lane .. 4*lane+3]
    *reinterpret_cast<float4*>(agg + (size_t)node * HID + 4 * lane) = acc;
}

// ---------------- fused dual GEMM + bias + relu (f32x2, float4 smem) --------
// optional fp16 copy of the output for the next layer's aggregation
template <int K>
__global__ __launch_bounds__(256, 1) void k_gemm_dual(
    const float* __restrict__ A, const float* __restrict__ X,
    const float* __restrict__ Wrel, const float* __restrict__ Wroot,
    const float* __restrict__ bias, float* __restrict__ out,
    __half* __restrict__ outh)
{
    constexpr int K4 = K / 4;
    constexpr int Kpad = K + 4;
    extern __shared__ __align__(16) float sm[];
    float4* Wr4 = (float4*)sm;                 // [K4][129]
    float4* Wt4 = Wr4 + K4 * 129;              // [K4][129]
    float* Aagg = (float*)(Wt4 + K4 * 129);    // [64][Kpad]
    float* Ax   = Aagg + 64 * Kpad;            // [64][Kpad]
    float* bs   = Ax + 64 * Kpad;              // [128]

    int t = threadIdx.x;
    int row0 = blockIdx.x * 64;

    for (int s = t; s < 128 * K4; s += 256) {
        int c = s / K4;
        int k4 = s - c * K4;
        Wr4[k4 * 129 + c] = *(const float4*)(Wrel + c * K + 4 * k4);
        Wt4[k4 * 129 + c] = *(const float4*)(Wroot + c * K + 4 * k4);
    }
    for (int s = t; s < 64 * K4; s += 256) {
        int r = s / K4;
        int k4 = s - r * K4;
        int row = row0 + r;
        float4 va = make_float4(0.f, 0.f, 0.f, 0.f);
        float4 vx = va;
        if (row < NN) {
            va = *(const float4*)(A + (size_t)row * K + 4 * k4);
            vx = *(const float4*)(X + (size_t)row * K + 4 * k4);
        }
        *(float4*)(Aagg + r * Kpad + 4 * k4) = va;
        *(float4*)(Ax   + r * Kpad + 4 * k4) = vx;
    }
    if (t < 128) bs[t] = bias[t];
    __syncthreads();

    int tc = t & 31;
    int tr = t >> 5;
    ull acc[8][4];
#pragma unroll
    for (int i = 0; i < 8; i++)
#pragma unroll
        for (int j = 0; j < 4; j++) acc[i][j] = 0ull;

    const float* Ar = Aagg + (tr * 8) * Kpad;
    const float* Xr = Ax + (tr * 8) * Kpad;

#pragma unroll 2
    for (int k4 = 0; k4 < K4; k4++) {
        ull wRl[4], wRh[4], wTl[4], wTh[4];
#pragma unroll
        for (int j = 0; j < 4; j++) {
            float4 w = Wr4[k4 * 129 + tc + 32 * j];
            wRl[j] = pk(w.x, w.y); wRh[j] = pk(w.z, w.w);
            float4 v = Wt4[k4 * 129 + tc + 32 * j];
            wTl[j] = pk(v.x, v.y); wTh[j] = pk(v.z, v.w);
        }
#pragma unroll
        for (int i = 0; i < 8; i++) {
            float4 a4 = *(const float4*)(Ar + i * Kpad + 4 * k4);
            float4 x4 = *(const float4*)(Xr + i * Kpad + 4 * k4);
            ull al = pk(a4.x, a4.y), ah = pk(a4.z, a4.w);
            ull xl = pk(x4.x, x4.y), xh = pk(x4.z, x4.w);
#pragma unroll
            for (int j = 0; j < 4; j++) {
                fma2(acc[i][j], al, wRl[j]);
                fma2(acc[i][j], ah, wRh[j]);
                fma2(acc[i][j], xl, wTl[j]);
                fma2(acc[i][j], xh, wTh[j]);
            }
        }
    }

#pragma unroll
    for (int i = 0; i < 8; i++) {
        int row = row0 + tr * 8 + i;
        if (row >= NN) continue;
#pragma unroll
        for (int j = 0; j < 4; j++) {
            int c = tc + 32 * j;
            float lo = __uint_as_float((unsigned)acc[i][j]);
            float hi = __uint_as_float((unsigned)(acc[i][j] >> 32));
            float v = fmaxf(lo + hi + bs[c], 0.f);
            out[(size_t)row * HID + c] = v;
            if (outh) outh[(size_t)row * HID + c] = __float2half_rn(v);
        }
    }
}

// ---------------- head GEMM: 64 nodes x 64 cols (47 used), K=384 ------------
__global__ __launch_bounds__(256, 1) void k_head(
    const float* __restrict__ Wlin, const float* __restrict__ blin,
    float* __restrict__ out)
{
    constexpr int K = 384, K4 = 96, Kpad = 388;
    extern __shared__ __align__(16) float sm[];
    float4* W4 = (float4*)sm;              // [K4][65]
    float* Xs = (float*)(W4 + K4 * 65);    // [64][Kpad]
    float* bs = Xs + 64 * Kpad;            // [64]

    int t = threadIdx.x;
    int row0 = blockIdx.x * 64;

    for (int s = t; s < 64 * K4; s += 256) {
        int c = s / K4;
        int k4 = s - c * K4;
        float4 v = make_float4(0.f, 0.f, 0.f, 0.f);
        if (c < CLS) v = *(const float4*)(Wlin + c * K + 4 * k4);
        W4[k4 * 65 + c] = v;
    }
    for (int s = t; s < 64 * K4; s += 256) {
        int r = s / K4;
        int k4 = s - r * K4;
        int row = row0 + r;
        float4 v = make_float4(0.f, 0.f, 0.f, 0.f);
        if (row < NN) {
            if (k4 < 32)      v = *(const float4*)(g_x1 + (size_t)row * HID + 4 * k4);
            else if (k4 < 64) v = *(const float4*)(g_x2 + (size_t)row * HID + 4 * (k4 - 32));
            else              v = *(const float4*)(g_x3 + (size_t)row * HID + 4 * (k4 - 64));
        }
        *(float4*)(Xs + r * Kpad + 4 * k4) = v;
    }
    if (t < 64) bs[t] = (t < CLS) ? blin[t] : 0.f;
    __syncthreads();

    int tc = t & 31;
    int tr = t >> 5;
    ull acc[8][2];
#pragma unroll
    for (int i = 0; i < 8; i++) { acc[i][0] = 0ull; acc[i][1] = 0ull; }

    const float* Xr = Xs + (tr * 8) * Kpad;

#pragma unroll 2
    for (int k4 = 0; k4 < K4; k4++) {
        ull wl[2], wh[2];
#pragma unroll
        for (int j = 0; j < 2; j++) {
            float4 w = W4[k4 * 65 + tc + 32 * j];
            wl[j] = pk(w.x, w.y); wh[j] = pk(w.z, w.w);
        }
#pragma unroll
        for (int i = 0; i < 8; i++) {
            float4 a4 = *(const float4*)(Xr + i * Kpad + 4 * k4);
            ull al = pk(a4.x, a4.y), ah = pk(a4.z, a4.w);
#pragma unroll
            for (int j = 0; j < 2; j++) {
                fma2(acc[i][j], al, wl[j]);
                fma2(acc[i][j], ah, wh[j]);
            }
        }
    }

    bool valid1 = (tc + 32) < CLS;
#pragma unroll
    for (int i = 0; i < 8; i++) {
        int row = row0 + tr * 8 + i;
        float v0 = __uint_as_float((unsigned)acc[i][0]) +
                   __uint_as_float((unsigned)(acc[i][0] >> 32)) + bs[tc];
        float v1 = __uint_as_float((unsigned)acc[i][1]) +
                   __uint_as_float((unsigned)(acc[i][1] >> 32)) + bs[tc + 32];
        float m = valid1 ? fmaxf(v0, v1) : v0;
#pragma unroll
        for (int o = 16; o > 0; o >>= 1) m = fmaxf(m, __shfl_xor_sync(0xffffffffu, m, o));
        float se = expf(v0 - m) + (valid1 ? expf(v1 - m) : 0.f);
#pragma unroll
        for (int o = 16; o > 0; o >>= 1) se += __shfl_xor_sync(0xffffffffu, se, o);
        float lse = m + logf(se);
        if (row < NN) {
            out[(size_t)row * CLS + tc] = v0 - lse;
            if (valid1) out[(size_t)row * CLS + tc + 32] = v1 - lse;
        }
    }
}

// ---------------- launch ----------------
extern "C" void kernel_launch(void* const* d_in, const int* in_sizes, int n_in,
                              void* d_out, int out_size)
{
    const float* x0    = (const float*)d_in[0];
    const int*   ei    = (const int*)  d_in[1];
    const float* ew    = (const float*)d_in[2];
    const float* W1rel = (const float*)d_in[3];
    const float* W1rt  = (const float*)d_in[4];
    const float* b1    = (const float*)d_in[5];
    const float* W2rel = (const float*)d_in[6];
    const float* W2rt  = (const float*)d_in[7];
    const float* b2    = (const float*)d_in[8];
    const float* W3rel = (const float*)d_in[9];
    const float* W3rt  = (const float*)d_in[10];
    const float* b3    = (const float*)d_in[11];
    const float* Wlin  = (const float*)d_in[12];
    const float* blin  = (const float*)d_in[13];
    float* out = (float*)d_out;

    const int* src = ei;
    const int* dst = ei + EE;

    float *agg0p, *aggp, *x1p, *x2p, *x3p;
    int* degp;
    __half *h1p, *h2p;
    cudaGetSymbolAddress((void**)&agg0p, g_agg0);
    cudaGetSymbolAddress((void**)&aggp,  g_agg);
    cudaGetSymbolAddress((void**)&x1p,   g_x1);
    cudaGetSymbolAddress((void**)&x2p,   g_x2);
    cudaGetSymbolAddress((void**)&x3p,   g_x3);
    cudaGetSymbolAddress((void**)&degp,  g_deg);
    cudaGetSymbolAddress((void**)&h1p,   g_h1);
    cudaGetSymbolAddress((void**)&h2p,   g_h2);

    const int smem128 = (2 * 129 * 32) * 16 + (2 * 64 * 132) * 4 + 512;  // 200192
    const int smem100 = (2 * 129 * 25) * 16 + (2 * 64 * 104) * 4 + 512;  // 156960
    const int smemH   = (96 * 65) * 16 + (64 * 388) * 4 + 256;           // 199424
    cudaFuncSetAttribute(k_gemm_dual<128>, cudaFuncAttributeMaxDynamicSharedMemorySize, smem128);
    cudaFuncSetAttribute(k_gemm_dual<100>, cudaFuncAttributeMaxDynamicSharedMemorySize, smem100);
    cudaFuncSetAttribute(k_head,           cudaFuncAttributeMaxDynamicSharedMemorySize, smemH);

    // CSR build: memset node + 3 kernels  -> launch #4 is k_aggregate<FIN>
    cudaMemsetAsync(degp, 0, NN * sizeof(int));
    k_count<<<(EE + 511) / 512, 512>>>(dst);                 // 1
    k_scanA<<<(NN + 1023) / 1024, 1024>>>();                 // 2
    k_fill<<<(EE + 511) / 512, 512>>>(src, dst, ew);         // 3

    const int aggBlocks = NN * 32 / 256;
    const int gemmBlocks = (NN + 63) / 64;

    // layer 1 (K = 100, fp32 gather)
    k_aggregate<FIN><<<aggBlocks, 256>>>(x0, agg0p);         // 4  <- profiled
    k_gemm_dual<100><<<gemmBlocks, 256, smem100>>>(agg0p, x0, W1rel, W1rt, b1, x1p, h1p);
    // layer 2 (fp16 gather)
    k_agg_h<<<aggBlocks, 256>>>(h1p, aggp);
    k_gemm_dual<128><<<gemmBlocks, 256, smem128>>>(aggp, x1p, W2rel, W2rt, b2, x2p, h2p);
    // layer 3 (fp16 gather)
    k_agg_h<<<aggBlocks, 256>>>(h2p, aggp);
    k_gemm_dual<128><<<gemmBlocks, 256, smem128>>>(aggp, x2p, W3rel, W3rt, b3, x3p, (__half*)nullptr);
    // head
    k_head<<<(NN + 63) / 64, 256, smemH>>>(Wlin, blin, out);
}

// round 5
// speedup vs baseline: 2.6307x; 2.5603x over previous
#include <cuda_runtime.h>
#include <cuda_fp16.h>

#define NN 100000
#define EE 1600000
#define HID 128
#define FIN 100
#define CLS 47

typedef unsigned long long ull;
typedef unsigned int uint;

// ---------------- device scratch (no allocs allowed) ----------------
__device__ int    g_deg[NN];
__device__ int    g_rowstart[NN];   // within-block exclusive (local) offsets
__device__ int    g_pos[NN];
__device__ int    g_bsums[128];
__device__ ull    g_perm[EE];       // packed: low32 = src, high32 = w bits
__device__ __half g_x0h [(size_t)NN * HID];   // x0 fp16, zero-padded 100->128
__device__ __half g_aggh[(size_t)NN * HID];   // aggregation output (fp16)
__device__ __half g_h1  [(size_t)NN * HID];
__device__ __half g_h2  [(size_t)NN * HID];
__device__ __half g_h3  [(size_t)NN * HID];

// 128-wide exclusive scan of g_bsums into se[]; all threads must hit barriers.
#define BSUM_SCAN(sb, se)                                            \
    {                                                                \
        int _t = threadIdx.x;                                        \
        if (_t < 128) sb[_t] = g_bsums[_t];                          \
        __syncthreads();                                             \
        for (int off = 1; off < 128; off <<= 1) {                    \
            int _a = 0, _b = 0;                                      \
            if (_t < 128) { _a = sb[_t]; _b = (_t >= off) ? sb[_t - off] : 0; } \
            __syncthreads();                                         \
            if (_t < 128) sb[_t] = _a + _b;                          \
            __syncthreads();                                         \
        }                                                            \
        if (_t < 128) se[_t] = sb[_t] - g_bsums[_t];                 \
        __syncthreads();                                             \
    }

__device__ __forceinline__ void mma16816(float* c, const uint* a, uint b0, uint b1) {
    asm volatile(
        "mma.sync.aligned.m16n8k16.row.col.f32.f16.f16.f32 "
        "{%0,%1,%2,%3}, {%4,%5,%6,%7}, {%8,%9}, {%0,%1,%2,%3};"
        : "+f"(c[0]), "+f"(c[1]), "+f"(c[2]), "+f"(c[3])
        : "r"(a[0]), "r"(a[1]), "r"(a[2]), "r"(a[3]), "r"(b0), "r"(b1));
}

// ---------------- x0 -> fp16 padded [N,128] ----------------
__global__ __launch_bounds__(256) void k_cvt_x0(const float* __restrict__ x0) {
    int gt = blockIdx.x * 256 + threadIdx.x;
    int node = gt >> 5;
    int lane = gt & 31;
    if (node >= NN) return;
    uint2 o = make_uint2(0u, 0u);
    if (lane < 25) {
        float4 v = __ldg(reinterpret_cast<const float4*>(x0 + (size_t)node * FIN) + lane);
        __half2 lo = __floats2half2_rn(v.x, v.y);
        __half2 hi = __floats2half2_rn(v.z, v.w);
        o.x = *(uint*)&lo; o.y = *(uint*)&hi;
    }
    *reinterpret_cast<uint2*>(g_x0h + (size_t)node * HID + 4 * lane) = o;
}

// ---------------- CSR build ----------------
__global__ void k_count(const int* __restrict__ dst) {
    int e = blockIdx.x * 512 + threadIdx.x;
    if (e < EE) atomicAdd(&g_deg[dst[e]], 1);
}

__global__ void k_scanA() {
    __shared__ int s[1024];
    int tid = threadIdx.x;
    int i = blockIdx.x * 1024 + tid;
    int v = (i < NN) ? g_deg[i] : 0;
    s[tid] = v;
    __syncthreads();
    for (int off = 1; off < 1024; off <<= 1) {
        int a = s[tid];
        int b = (tid >= off) ? s[tid - off] : 0;
        __syncthreads();
        s[tid] = a + b;
        __syncthreads();
    }
    if (i < NN) {
        int loc = s[tid] - v;
        g_rowstart[i] = loc;
        g_pos[i] = loc;
    }
    if (tid == 1023) g_bsums[blockIdx.x] = s[1023];
}

__global__ void k_fill(const int* __restrict__ src, const int* __restrict__ dst,
                       const float* __restrict__ w) {
    __shared__ int sb[128];
    __shared__ int se[128];
    BSUM_SCAN(sb, se);
    int e = blockIdx.x * 512 + threadIdx.x;
    if (e >= EE) return;
    int d = dst[e];
    int p = atomicAdd(&g_pos[d], 1) + se[d >> 10];
    g_perm[p] = ((ull)__float_as_uint(w[e]) << 32) | (unsigned)src[e];
}

// ---------------- aggregation: fp16 gather, fp32 accum, fp16 out ------------
// NV = active lanes (25 for D=100, 32 for D=128); row stride always 128 halves
template <int NV>
__global__ __launch_bounds__(256) void k_agg_h(
    const __half* __restrict__ x, __half* __restrict__ agg)
{
    __shared__ int sb[128];
    __shared__ int se[128];
    BSUM_SCAN(sb, se);
    int gt = blockIdx.x * 256 + threadIdx.x;
    int node = gt >> 5;
    int lane = gt & 31;
    if (node >= NN) return;
    int start = g_rowstart[node] + se[node >> 10];
    int cnt = g_deg[node];
    bool act = (NV == 32) || (lane < NV);
    float4 acc = make_float4(0.f, 0.f, 0.f, 0.f);
    int i = 0;
    for (; i + 4 <= cnt; i += 4) {
        ull e0 = __ldg(&g_perm[start + i + 0]);
        ull e1 = __ldg(&g_perm[start + i + 1]);
        ull e2 = __ldg(&g_perm[start + i + 2]);
        ull e3 = __ldg(&g_perm[start + i + 3]);
        int s0 = (int)(unsigned)e0, s1 = (int)(unsigned)e1;
        int s2 = (int)(unsigned)e2, s3 = (int)(unsigned)e3;
        float w0 = __uint_as_float((unsigned)(e0 >> 32));
        float w1 = __uint_as_float((unsigned)(e1 >> 32));
        float w2 = __uint_as_float((unsigned)(e2 >> 32));
        float w3 = __uint_as_float((unsigned)(e3 >> 32));
        if (act) {
            uint2 v0 = __ldg(reinterpret_cast<const uint2*>(x + (size_t)s0 * HID) + lane);
            uint2 v1 = __ldg(reinterpret_cast<const uint2*>(x + (size_t)s1 * HID) + lane);
            uint2 v2 = __ldg(reinterpret_cast<const uint2*>(x + (size_t)s2 * HID) + lane);
            uint2 v3 = __ldg(reinterpret_cast<const uint2*>(x + (size_t)s3 * HID) + lane);
            float2 a0 = __half22float2(*(__half2*)&v0.x), b0 = __half22float2(*(__half2*)&v0.y);
            float2 a1 = __half22float2(*(__half2*)&v1.x), b1 = __half22float2(*(__half2*)&v1.y);
            float2 a2 = __half22float2(*(__half2*)&v2.x), b2 = __half22float2(*(__half2*)&v2.y);
            float2 a3 = __half22float2(*(__half2*)&v3.x), b3 = __half22float2(*(__half2*)&v3.y);
            acc.x += a0.x * w0 + a1.x * w1 + a2.x * w2 + a3.x * w3;
            acc.y += a0.y * w0 + a1.y * w1 + a2.y * w2 + a3.y * w3;
            acc.z += b0.x * w0 + b1.x * w1 + b2.x * w2 + b3.x * w3;
            acc.w += b0.y * w0 + b1.y * w1 + b2.y * w2 + b3.y * w3;
        }
    }
    for (; i < cnt; i++) {
        ull e = __ldg(&g_perm[start + i]);
        int s = (int)(unsigned)e;
        float wv = __uint_as_float((unsigned)(e >> 32));
        if (act) {
            uint2 v = __ldg(reinterpret_cast<const uint2*>(x + (size_t)s * HID) + lane);
            float2 a = __half22float2(*(__half2*)&v.x), b = __half22float2(*(__half2*)&v.y);
            acc.x += a.x * wv; acc.y += a.y * wv; acc.z += b.x * wv; acc.w += b.y * wv;
        }
    }
    uint2 o = make_uint2(0u, 0u);
    if (act) {
        __half2 lo = __floats2half2_rn(acc.x, acc.y);
        __half2 hi = __floats2half2_rn(acc.z, acc.w);
        o.x = *(uint*)&lo; o.y = *(uint*)&hi;
    }
    *reinterpret_cast<uint2*>(agg + (size_t)node * HID + 4 * lane) = o;
}

// ---------------- dual GEMM via HMMA: out = relu(A@Wrel^T + X@Wroot^T + b) --
// Block: 128 rows x 128 cols, 256 threads (8 warps: 4 m-warps x 2 n-warps).
// Warp tile 32x64 = 2 m16 x 8 n8 mma tiles, K = 128 (8 k16 steps).
// Weights fp32 [128][KREAL] converted to fp16 in smem (zero-padded K->128).
template <int KREAL>
__global__ __launch_bounds__(256, 1) void k_gemm_mma(
    const __half* __restrict__ A, const __half* __restrict__ X,
    const float* __restrict__ Wrel, const float* __restrict__ Wroot,
    const float* __restrict__ bias, __half* __restrict__ out)
{
    constexpr int LDS = 136;   // half stride, +8 pad
    extern __shared__ __align__(16) char smraw[];
    __half* As = (__half*)smraw;           // [128][136]
    __half* Xs = As + 128 * LDS;
    __half* Wr = Xs + 128 * LDS;
    __half* Wt = Wr + 128 * LDS;
    float*  bs = (float*)(Wt + 128 * LDS); // [128]

    int t = threadIdx.x;
    int row0 = blockIdx.x * 128;

    // A/X tiles: [128][128] halves as uint4 (8 halves) chunks
    for (int s = t; s < 128 * 16; s += 256) {
        int r = s >> 4;
        int q = s & 15;
        int row = row0 + r;
        uint4 va = make_uint4(0u, 0u, 0u, 0u), vx = va;
        if (row < NN) {
            va = *reinterpret_cast<const uint4*>(A + (size_t)row * HID + q * 8);
            vx = *reinterpret_cast<const uint4*>(X + (size_t)row * HID + q * 8);
        }
        *reinterpret_cast<uint4*>(As + r * LDS + q * 8) = va;
        *reinterpret_cast<uint4*>(Xs + r * LDS + q * 8) = vx;
    }
    // weights: fp32 -> fp16, zero-pad k >= KREAL
    for (int s = t; s < 128 * 32; s += 256) {
        int c = s >> 5;
        int k4 = s & 31;
        float4 wr = make_float4(0.f, 0.f, 0.f, 0.f), wt = wr;
        if (4 * k4 < KREAL) {
            wr = *reinterpret_cast<const float4*>(Wrel + (size_t)c * KREAL + 4 * k4);
            wt = *reinterpret_cast<const float4*>(Wroot + (size_t)c * KREAL + 4 * k4);
        }
        __half2 r0 = __floats2half2_rn(wr.x, wr.y), r1 = __floats2half2_rn(wr.z, wr.w);
        __half2 t0 = __floats2half2_rn(wt.x, wt.y), t1 = __floats2half2_rn(wt.z, wt.w);
        *reinterpret_cast<uint2*>(Wr + c * LDS + 4 * k4) = make_uint2(*(uint*)&r0, *(uint*)&r1);
        *reinterpret_cast<uint2*>(Wt + c * LDS + 4 * k4) = make_uint2(*(uint*)&t0, *(uint*)&t1);
    }
    if (t < 128) bs[t] = bias[t];
    __syncthreads();

    int lane = t & 31;
    int wid = t >> 5;
    int wm = (wid & 3) * 32;     // warp m-offset (rows)
    int wn = (wid >> 2) * 64;    // warp n-offset (cols)
    int g = lane >> 2;
    int tg = lane & 3;

    float acc[2][8][4];
#pragma unroll
    for (int mt = 0; mt < 2; mt++)
#pragma unroll
        for (int nt = 0; nt < 8; nt++)
#pragma unroll
            for (int q = 0; q < 4; q++) acc[mt][nt][q] = 0.f;

#pragma unroll
    for (int kk = 0; kk < 8; kk++) {
        int kc = kk * 16 + tg * 2;
        uint a[2][4], xx[2][4];
#pragma unroll
        for (int mt = 0; mt < 2; mt++) {
            int m = wm + mt * 16;
            a[mt][0] = *(uint*)&As[(m + g) * LDS + kc];
            a[mt][1] = *(uint*)&As[(m + g + 8) * LDS + kc];
            a[mt][2] = *(uint*)&As[(m + g) * LDS + kc + 8];
            a[mt][3] = *(uint*)&As[(m + g + 8) * LDS + kc + 8];
            xx[mt][0] = *(uint*)&Xs[(m + g) * LDS + kc];
            xx[mt][1] = *(uint*)&Xs[(m + g + 8) * LDS + kc];
            xx[mt][2] = *(uint*)&Xs[(m + g) * LDS + kc + 8];
            xx[mt][3] = *(uint*)&Xs[(m + g + 8) * LDS + kc + 8];
        }
#pragma unroll
        for (int nt = 0; nt < 8; nt++) {
            int n = wn + nt * 8;
            uint bR0 = *(uint*)&Wr[(n + g) * LDS + kc];
            uint bR1 = *(uint*)&Wr[(n + g) * LDS + kc + 8];
            uint bT0 = *(uint*)&Wt[(n + g) * LDS + kc];
            uint bT1 = *(uint*)&Wt[(n + g) * LDS + kc + 8];
            mma16816(acc[0][nt], a[0], bR0, bR1);
            mma16816(acc[1][nt], a[1], bR0, bR1);
            mma16816(acc[0][nt], xx[0], bT0, bT1);
            mma16816(acc[1][nt], xx[1], bT0, bT1);
        }
    }

    // epilogue: bias + relu -> fp16
#pragma unroll
    for (int mt = 0; mt < 2; mt++) {
        int r0r = row0 + wm + mt * 16 + g;
        int r1r = r0r + 8;
#pragma unroll
        for (int nt = 0; nt < 8; nt++) {
            int c = wn + nt * 8 + tg * 2;
            float b0 = bs[c], b1 = bs[c + 1];
            if (r0r < NN) {
                __half2 h = __floats2half2_rn(fmaxf(acc[mt][nt][0] + b0, 0.f),
                                              fmaxf(acc[mt][nt][1] + b1, 0.f));
                *reinterpret_cast<__half2*>(out + (size_t)r0r * HID + c) = h;
            }
            if (r1r < NN) {
                __half2 h = __floats2half2_rn(fmaxf(acc[mt][nt][2] + b0, 0.f),
                                              fmaxf(acc[mt][nt][3] + b1, 0.f));
                *reinterpret_cast<__half2*>(out + (size_t)r1r * HID + c) = h;
            }
        }
    }
}

// ---------------- head via HMMA: [x1|x2|x3] @ Wlin^T + b, log_softmax -------
// Block: 128 rows x 64 cols (47 real), 8 warps, warp = 16 rows x 64 cols.
__global__ __launch_bounds__(256, 1) void k_head_mma(
    const float* __restrict__ Wlin, const float* __restrict__ blin,
    float* __restrict__ out)
{
    constexpr int K = 384, LDS = 392;
    extern __shared__ __align__(16) char smraw[];
    __half* Xs = (__half*)smraw;            // [128][392]
    __half* Ws = Xs + 128 * LDS;            // [64][392]
    float*  bs = (float*)(Ws + 64 * LDS);   // [64]

    int t = threadIdx.x;
    int row0 = blockIdx.x * 128;

    // X tile: concat of g_h1|g_h2|g_h3, 48 uint4-chunks per row
    for (int s = t; s < 128 * 48; s += 256) {
        int r = s / 48;
        int q = s - r * 48;
        int row = row0 + r;
        uint4 v = make_uint4(0u, 0u, 0u, 0u);
        if (row < NN) {
            const __half* srcp = (q < 16) ? g_h1 : (q < 32) ? g_h2 : g_h3;
            int qq = q & 15;
            v = *reinterpret_cast<const uint4*>(srcp + (size_t)row * HID + qq * 8);
        }
        *reinterpret_cast<uint4*>(Xs + r * LDS + q * 8) = v;
    }
    // weights: [47][384] fp32 -> [64][384] fp16 zero-padded
    for (int s = t; s < 64 * 96; s += 256) {
        int c = s / 96;
        int k4 = s - c * 96;
        float4 w = make_float4(0.f, 0.f, 0.f, 0.f);
        if (c < CLS) w = *reinterpret_cast<const float4*>(Wlin + (size_t)c * K + 4 * k4);
        __half2 w0 = __floats2half2_rn(w.x, w.y), w1 = __floats2half2_rn(w.z, w.w);
        *reinterpret_cast<uint2*>(Ws + c * LDS + 4 * k4) = make_uint2(*(uint*)&w0, *(uint*)&w1);
    }
    if (t < 64) bs[t] = (t < CLS) ? blin[t] : 0.f;
    __syncthreads();

    int lane = t & 31;
    int wid = t >> 5;
    int m = wid * 16;
    int g = lane >> 2;
    int tg = lane & 3;

    float acc[8][4];
#pragma unroll
    for (int nt = 0; nt < 8; nt++)
#pragma unroll
        for (int q = 0; q < 4; q++) acc[nt][q] = 0.f;

#pragma unroll 4
    for (int kk = 0; kk < 24; kk++) {
        int kc = kk * 16 + tg * 2;
        uint a[4];
        a[0] = *(uint*)&Xs[(m + g) * LDS + kc];
        a[1] = *(uint*)&Xs[(m + g + 8) * LDS + kc];
        a[2] = *(uint*)&Xs[(m + g) * LDS + kc + 8];
        a[3] = *(uint*)&Xs[(m + g + 8) * LDS + kc + 8];
#pragma unroll
        for (int nt = 0; nt < 8; nt++) {
            int n = nt * 8;
            uint b0 = *(uint*)&Ws[(n + g) * LDS + kc];
            uint b1 = *(uint*)&Ws[(n + g) * LDS + kc + 8];
            mma16816(acc[nt], a, b0, b1);
        }
    }

    // log-softmax: each row's 64 cols live in 4 threads (same g, tg=0..3).
    // rows r0 (= m+g) use acc[.][0..1], rows r0+8 use acc[.][2..3].
#pragma unroll
    for (int half = 0; half < 2; half++) {
        int row = row0 + m + g + half * 8;
        float v[8][2];
        float mx = -1e30f;
#pragma unroll
        for (int nt = 0; nt < 8; nt++) {
            int c = nt * 8 + tg * 2;
            float a0 = acc[nt][half * 2 + 0] + bs[c];
            float a1 = acc[nt][half * 2 + 1] + bs[c + 1];
            v[nt][0] = a0; v[nt][1] = a1;
            if (c < CLS) mx = fmaxf(mx, a0);
            if (c + 1 < CLS) mx = fmaxf(mx, a1);
        }
        mx = fmaxf(mx, __shfl_xor_sync(0xffffffffu, mx, 1));
        mx = fmaxf(mx, __shfl_xor_sync(0xffffffffu, mx, 2));
        float se = 0.f;
#pragma unroll
        for (int nt = 0; nt < 8; nt++) {
            int c = nt * 8 + tg * 2;
            if (c < CLS) se += expf(v[nt][0] - mx);
            if (c + 1 < CLS) se += expf(v[nt][1] - mx);
        }
        se += __shfl_xor_sync(0xffffffffu, se, 1);
        se += __shfl_xor_sync(0xffffffffu, se, 2);
        float lse = mx + logf(se);
        if (row < NN) {
#pragma unroll
            for (int nt = 0; nt < 8; nt++) {
                int c = nt * 8 + tg * 2;
                if (c < CLS) out[(size_t)row * CLS + c] = v[nt][0] - lse;
                if (c + 1 < CLS) out[(size_t)row * CLS + c + 1] = v[nt][1] - lse;
            }
        }
    }
}

// ---------------- launch ----------------
extern "C" void kernel_launch(void* const* d_in, const int* in_sizes, int n_in,
                              void* d_out, int out_size)
{
    const float* x0    = (const float*)d_in[0];
    const int*   ei    = (const int*)  d_in[1];
    const float* ew    = (const float*)d_in[2];
    const float* W1rel = (const float*)d_in[3];
    const float* W1rt  = (const float*)d_in[4];
    const float* b1    = (const float*)d_in[5];
    const float* W2rel = (const float*)d_in[6];
    const float* W2rt  = (const float*)d_in[7];
    const float* b2    = (const float*)d_in[8];
    const float* W3rel = (const float*)d_in[9];
    const float* W3rt  = (const float*)d_in[10];
    const float* b3    = (const float*)d_in[11];
    const float* Wlin  = (const float*)d_in[12];
    const float* blin  = (const float*)d_in[13];
    float* out = (float*)d_out;

    const int* src = ei;
    const int* dst = ei + EE;

    int* degp;
    __half *x0hp, *agghp, *h1p, *h2p, *h3p;
    cudaGetSymbolAddress((void**)&degp,  g_deg);
    cudaGetSymbolAddress((void**)&x0hp,  g_x0h);
    cudaGetSymbolAddress((void**)&agghp, g_aggh);
    cudaGetSymbolAddress((void**)&h1p,   g_h1);
    cudaGetSymbolAddress((void**)&h2p,   g_h2);
    cudaGetSymbolAddress((void**)&h3p,   g_h3);

    const int smemG = 4 * 128 * 136 * 2 + 128 * 4 + 256;           // ~139.8 KB
    const int smemH = 128 * 392 * 2 + 64 * 392 * 2 + 64 * 4 + 256; // ~151 KB
    cudaFuncSetAttribute(k_gemm_mma<100>, cudaFuncAttributeMaxDynamicSharedMemorySize, smemG);
    cudaFuncSetAttribute(k_gemm_mma<128>, cudaFuncAttributeMaxDynamicSharedMemorySize, smemG);
    cudaFuncSetAttribute(k_head_mma,      cudaFuncAttributeMaxDynamicSharedMemorySize, smemH);

    cudaMemsetAsync(degp, 0, NN * sizeof(int));

    const int aggBlocks = NN * 32 / 256;        // 12500
    const int gemmBlocks = (NN + 127) / 128;    // 782

    k_cvt_x0<<<aggBlocks, 256>>>(x0);                        // 1
    k_count<<<(EE + 511) / 512, 512>>>(dst);                 // 2
    k_scanA<<<(NN + 1023) / 1024, 1024>>>();                 // 3
    k_fill<<<(EE + 511) / 512, 512>>>(src, dst, ew);         // 4 <- profiled

    // layer 1 (K=100 padded to 128)
    k_agg_h<25><<<aggBlocks, 256>>>(x0hp, agghp);
    k_gemm_mma<100><<<gemmBlocks, 256, smemG>>>(agghp, x0hp, W1rel, W1rt, b1, h1p);
    // layer 2
    k_agg_h<32><<<aggBlocks, 256>>>(h1p, agghp);
    k_gemm_mma<128><<<gemmBlocks, 256, smemG>>>(agghp, h1p, W2rel, W2rt, b2, h2p);
    // layer 3
    k_agg_h<32><<<aggBlocks, 256>>>(h2p, agghp);
    k_gemm_mma<128><<<gemmBlocks, 256, smemG>>>(agghp, h2p, W3rel, W3rt, b3, h3p);
    // head
    k_head_mma<<<gemmBlocks, 256, smemH>>>(Wlin, blin, out);
}

// round 9
// speedup vs baseline: 2.9863x; 1.1352x over previous
#include <cuda_runtime.h>
#include <cuda_fp16.h>
#include <cstdint>

#define NN 100000
#define EE 1600000
#define HID 128
#define FIN 100
#define CLS 47

typedef unsigned long long ull;
typedef unsigned int uint;

// ---------------- device scratch (no allocs allowed) ----------------
__device__ int    g_deg[NN];
__device__ int    g_rowstart[NN];
__device__ int    g_pos[NN];
__device__ int    g_bsums[128];
__device__ ull    g_perm[EE];                 // low32 = src, high32 = w bits
__device__ __half g_x0h [(size_t)NN * HID];   // x0 fp16, zero-padded 100->128
__device__ __half g_aggh[(size_t)NN * HID];
__device__ __half g_h1  [(size_t)NN * HID];
__device__ __half g_h2  [(size_t)NN * HID];
__device__ __half g_h3  [(size_t)NN * HID];
__device__ __half g_wh  [6 * 128 * 128];      // fp16 weights, K padded to 128

#define BSUM_SCAN(sb, se)                                            \
    {                                                                \
        int _t = threadIdx.x;                                        \
        if (_t < 128) sb[_t] = g_bsums[_t];                          \
        __syncthreads();                                             \
        for (int off = 1; off < 128; off <<= 1) {                    \
            int _a = 0, _b = 0;                                      \
            if (_t < 128) { _a = sb[_t]; _b = (_t >= off) ? sb[_t - off] : 0; } \
            __syncthreads();                                         \
            if (_t < 128) sb[_t] = _a + _b;                          \
            __syncthreads();                                         \
        }                                                            \
        if (_t < 128) se[_t] = sb[_t] - g_bsums[_t];                 \
        __syncthreads();                                             \
    }

__device__ __forceinline__ uint32_t smem_u32(const void* p) {
    uint32_t a;
    asm("{ .reg .u64 t; cvta.to.shared.u64 t, %1; cvt.u32.u64 %0, t; }" : "=r"(a) : "l"(p));
    return a;
}
__device__ __forceinline__ void mma16816(float* c, const uint* a, uint b0, uint b1) {
    asm volatile(
        "mma.sync.aligned.m16n8k16.row.col.f32.f16.f16.f32 "
        "{%0,%1,%2,%3}, {%4,%5,%6,%7}, {%8,%9}, {%0,%1,%2,%3};"
        : "+f"(c[0]), "+f"(c[1]), "+f"(c[2]), "+f"(c[3])
        : "r"(a[0]), "r"(a[1]), "r"(a[2]), "r"(a[3]), "r"(b0), "r"(b1));
}
__device__ __forceinline__ void ldsm4(uint* r, uint32_t a) {
    asm volatile("ldmatrix.sync.aligned.m8n8.x4.shared.b16 {%0,%1,%2,%3}, [%4];"
                 : "=r"(r[0]), "=r"(r[1]), "=r"(r[2]), "=r"(r[3]) : "r"(a));
}

// ---------------- k_pre: edge count + x0->fp16 + weights->fp16 --------------
#define NB_CNT 3125
#define NB_CVT 6250     // 6250 blocks * 16 warps = 100000 node-warps
#define NB_W   12
__global__ __launch_bounds__(512) void k_pre(
    const int* __restrict__ dst, const float* __restrict__ x0,
    const float* __restrict__ W1rel, const float* __restrict__ W1rt,
    const float* __restrict__ W2rel, const float* __restrict__ W2rt,
    const float* __restrict__ W3rel, const float* __restrict__ W3rt)
{
    int b = blockIdx.x;
    int t = threadIdx.x;
    if (b < NB_CNT) {
        int e = b * 512 + t;
        if (e < EE) atomicAdd(&g_deg[dst[e]], 1);
    } else if (b < NB_CNT + NB_CVT) {
        int node = (b - NB_CNT) * 16 + (t >> 5);
        int lane = t & 31;
        if (node >= NN) return;
        uint2 o = make_uint2(0u, 0u);
        if (lane < 25) {
            float4 v = __ldg(reinterpret_cast<const float4*>(x0 + (size_t)node * FIN) + lane);
            __half2 lo = __floats2half2_rn(v.x, v.y);
            __half2 hi = __floats2half2_rn(v.z, v.w);
            o.x = *(uint*)&lo; o.y = *(uint*)&hi;
        }
        *reinterpret_cast<uint2*>(g_x0h + (size_t)node * HID + 4 * lane) = o;
    } else {
        const float* ws[6] = {W1rel, W1rt, W2rel, W2rt, W3rel, W3rt};
        for (int e = (b - NB_CNT - NB_CVT) * 512 + t; e < 6 * 16384; e += NB_W * 512) {
            int m = e >> 14;
            int r = e & 16383;
            int c = r >> 7;
            int k = r & 127;
            int kreal = (m < 2) ? FIN : HID;
            float v = (k < kreal) ? ws[m][(size_t)c * kreal + k] : 0.f;
            g_wh[e] = __float2half_rn(v);
        }
    }
}

// ---------------- CSR scan + fill ----------------
__global__ void k_scanA() {
    __shared__ int s[1024];
    int tid = threadIdx.x;
    int i = blockIdx.x * 1024 + tid;
    int v = (i < NN) ? g_deg[i] : 0;
    s[tid] = v;
    __syncthreads();
    for (int off = 1; off < 1024; off <<= 1) {
        int a = s[tid];
        int b = (tid >= off) ? s[tid - off] : 0;
        __syncthreads();
        s[tid] = a + b;
        __syncthreads();
    }
    if (i < NN) {
        int loc = s[tid] - v;
        g_rowstart[i] = loc;
        g_pos[i] = loc;
    }
    if (tid == 1023) g_bsums[blockIdx.x] = s[1023];
}

__global__ void k_fill(const int* __restrict__ src, const int* __restrict__ dst,
                       const float* __restrict__ w) {
    __shared__ int sb[128];
    __shared__ int se[128];
    BSUM_SCAN(sb, se);
    int e = blockIdx.x * 512 + threadIdx.x;
    if (e >= EE) return;
    int d = dst[e];
    int p = atomicAdd(&g_pos[d], 1) + se[d >> 10];
    g_perm[p] = ((ull)__float_as_uint(w[e]) << 32) | (unsigned)src[e];
}

// ---------------- aggregation: fp16 gather, fp32 accum, fp16 out ------------
template <int NV>
__global__ __launch_bounds__(256) void k_agg_h(
    const __half* __restrict__ x, __half* __restrict__ agg)
{
    __shared__ int sb[128];
    __shared__ int se[128];
    BSUM_SCAN(sb, se);
    int gt = blockIdx.x * 256 + threadIdx.x;
    int node = gt >> 5;
    int lane = gt & 31;
    if (node >= NN) return;
    int start = g_rowstart[node] + se[node >> 10];
    int cnt = g_deg[node];
    bool act = (NV == 32) || (lane < NV);
    float4 acc = make_float4(0.f, 0.f, 0.f, 0.f);
    int i = 0;
    for (; i + 4 <= cnt; i += 4) {
        ull e0 = __ldg(&g_perm[start + i + 0]);
        ull e1 = __ldg(&g_perm[start + i + 1]);
        ull e2 = __ldg(&g_perm[start + i + 2]);
        ull e3 = __ldg(&g_perm[start + i + 3]);
        int s0 = (int)(unsigned)e0, s1 = (int)(unsigned)e1;
        int s2 = (int)(unsigned)e2, s3 = (int)(unsigned)e3;
        float w0 = __uint_as_float((unsigned)(e0 >> 32));
        float w1 = __uint_as_float((unsigned)(e1 >> 32));
        float w2 = __uint_as_float((unsigned)(e2 >> 32));
        float w3 = __uint_as_float((unsigned)(e3 >> 32));
        if (act) {
            uint2 v0 = __ldg(reinterpret_cast<const uint2*>(x + (size_t)s0 * HID) + lane);
            uint2 v1 = __ldg(reinterpret_cast<const uint2*>(x + (size_t)s1 * HID) + lane);
            uint2 v2 = __ldg(reinterpret_cast<const uint2*>(x + (size_t)s2 * HID) + lane);
            uint2 v3 = __ldg(reinterpret_cast<const uint2*>(x + (size_t)s3 * HID) + lane);
            float2 a0 = __half22float2(*(__half2*)&v0.x), b0 = __half22float2(*(__half2*)&v0.y);
            float2 a1 = __half22float2(*(__half2*)&v1.x), b1 = __half22float2(*(__half2*)&v1.y);
            float2 a2 = __half22float2(*(__half2*)&v2.x), b2 = __half22float2(*(__half2*)&v2.y);
            float2 a3 = __half22float2(*(__half2*)&v3.x), b3 = __half22float2(*(__half2*)&v3.y);
            acc.x += a0.x * w0 + a1.x * w1 + a2.x * w2 + a3.x * w3;
            acc.y += a0.y * w0 + a1.y * w1 + a2.y * w2 + a3.y * w3;
            acc.z += b0.x * w0 + b1.x * w1 + b2.x * w2 + b3.x * w3;
            acc.w += b0.y * w0 + b1.y * w1 + b2.y * w2 + b3.y * w3;
        }
    }
    for (; i < cnt; i++) {
        ull e = __ldg(&g_perm[start + i]);
        int s = (int)(unsigned)e;
        float wv = __uint_as_float((unsigned)(e >> 32));
        if (act) {
            uint2 v = __ldg(reinterpret_cast<const uint2*>(x + (size_t)s * HID) + lane);
            float2 a = __half22float2(*(__half2*)&v.x), b = __half22float2(*(__half2*)&v.y);
            acc.x += a.x * wv; acc.y += a.y * wv; acc.z += b.x * wv; acc.w += b.y * wv;
        }
    }
    uint2 o = make_uint2(0u, 0u);
    if (act) {
        __half2 lo = __floats2half2_rn(acc.x, acc.y);
        __half2 hi = __floats2half2_rn(acc.z, acc.w);
        o.x = *(uint*)&lo; o.y = *(uint*)&hi;
    }
    *reinterpret_cast<uint2*>(agg + (size_t)node * HID + 4 * lane) = o;
}

// ---------------- dual GEMM via HMMA + ldmatrix -----------------------------
// Block 128x128, 8 warps (4 m-warps x 2 n-warps), warp tile 32x64.
__global__ __launch_bounds__(256, 1) void k_gemm_mma(
    const __half* __restrict__ A, const __half* __restrict__ X,
    const __half* __restrict__ Wr, const __half* __restrict__ Wt,
    const float* __restrict__ bias, __half* __restrict__ out)
{
    constexpr int LDS = 136;   // half stride (272 B, 16B-aligned rows)
    extern __shared__ __align__(16) char smraw[];
    __half* As = (__half*)smraw;           // [128][136]
    __half* Xs = As + 128 * LDS;
    __half* Wrs = Xs + 128 * LDS;
    __half* Wts = Wrs + 128 * LDS;
    float*  bs = (float*)(Wts + 128 * LDS);

    int t = threadIdx.x;
    int row0 = blockIdx.x * 128;

    for (int s = t; s < 128 * 16; s += 256) {
        int r = s >> 4;
        int q = s & 15;
        int row = row0 + r;
        uint4 va = make_uint4(0u, 0u, 0u, 0u), vx = va;
        if (row < NN) {
            va = *reinterpret_cast<const uint4*>(A + (size_t)row * HID + q * 8);
            vx = *reinterpret_cast<const uint4*>(X + (size_t)row * HID + q * 8);
        }
        *reinterpret_cast<uint4*>(As + r * LDS + q * 8) = va;
        *reinterpret_cast<uint4*>(Xs + r * LDS + q * 8) = vx;
        *reinterpret_cast<uint4*>(Wrs + r * LDS + q * 8) =
            *reinterpret_cast<const uint4*>(Wr + (size_t)r * HID + q * 8);
        *reinterpret_cast<uint4*>(Wts + r * LDS + q * 8) =
            *reinterpret_cast<const uint4*>(Wt + (size_t)r * HID + q * 8);
    }
    if (t < 128) bs[t] = bias[t];
    __syncthreads();

    int lane = t & 31;
    int wid = t >> 5;
    int wm = (wid & 3) * 32;
    int wn = (wid >> 2) * 64;
    int g = lane >> 2;
    int tg = lane & 3;

    // A/X x4: lanes 0-15 -> rows m0..15 (k0), lanes 16-31 -> rows m0..15 (k8)
    uint32_t a_row = wm + (lane & 15);
    uint32_t a_col = (lane >> 4) * 8;
    uint32_t adA0 = smem_u32(As + (a_row)      * LDS + a_col);
    uint32_t adA1 = smem_u32(As + (a_row + 16) * LDS + a_col);
    uint32_t adX0 = smem_u32(Xs + (a_row)      * LDS + a_col);
    uint32_t adX1 = smem_u32(Xs + (a_row + 16) * LDS + a_col);
    // B x4: m0 = n0-7/k0-7, m1 = n0-7/k8-15, m2 = n8-15/k0-7, m3 = n8-15/k8-15
    uint32_t b_row = (lane & 7) + ((lane >> 4) << 3);
    uint32_t b_col = ((lane >> 3) & 1) * 8;
    uint32_t adWr[4], adWt[4];
#pragma unroll
    for (int j = 0; j < 4; j++) {
        adWr[j] = smem_u32(Wrs + (wn + j * 16 + b_row) * LDS + b_col);
        adWt[j] = smem_u32(Wts + (wn + j * 16 + b_row) * LDS + b_col);
    }

    float acc[2][8][4];
#pragma unroll
    for (int mt = 0; mt < 2; mt++)
#pragma unroll
        for (int nt = 0; nt < 8; nt++)
#pragma unroll
            for (int q = 0; q < 4; q++) acc[mt][nt][q] = 0.f;

#pragma unroll
    for (int kk = 0; kk < 8; kk++) {
        uint32_t ko = kk * 32;   // 16 halves
        uint a0[4], a1[4], x0f[4], x1f[4];
        ldsm4(a0, adA0 + ko);
        ldsm4(a1, adA1 + ko);
        ldsm4(x0f, adX0 + ko);
        ldsm4(x1f, adX1 + ko);
#pragma unroll
        for (int j = 0; j < 4; j++) {
            uint wr[4], wt[4];
            ldsm4(wr, adWr[j] + ko);
            ldsm4(wt, adWt[j] + ko);
            mma16816(acc[0][2 * j],     a0, wr[0], wr[1]);
            mma16816(acc[1][2 * j],     a1, wr[0], wr[1]);
            mma16816(acc[0][2 * j + 1], a0, wr[2], wr[3]);
            mma16816(acc[1][2 * j + 1], a1, wr[2], wr[3]);
            mma16816(acc[0][2 * j],     x0f, wt[0], wt[1]);
            mma16816(acc[1][2 * j],     x1f, wt[0], wt[1]);
            mma16816(acc[0][2 * j + 1], x0f, wt[2], wt[3]);
            mma16816(acc[1][2 * j + 1], x1f, wt[2], wt[3]);
        }
    }

#pragma unroll
    for (int mt = 0; mt < 2; mt++) {
        int r0r = row0 + wm + mt * 16 + g;
        int r1r = r0r + 8;
#pragma unroll
        for (int nt = 0; nt < 8; nt++) {
            int c = wn + nt * 8 + tg * 2;
            float b0 = bs[c], b1 = bs[c + 1];
            if (r0r < NN) {
                __half2 h = __floats2half2_rn(fmaxf(acc[mt][nt][0] + b0, 0.f),
                                              fmaxf(acc[mt][nt][1] + b1, 0.f));
                *reinterpret_cast<__half2*>(out + (size_t)r0r * HID + c) = h;
            }
            if (r1r < NN) {
                __half2 h = __floats2half2_rn(fmaxf(acc[mt][nt][2] + b0, 0.f),
                                              fmaxf(acc[mt][nt][3] + b1, 0.f));
                *reinterpret_cast<__half2*>(out + (size_t)r1r * HID + c) = h;
            }
        }
    }
}

// ---------------- head via HMMA + ldmatrix ----------------------------------
__global__ __launch_bounds__(256, 1) void k_head_mma(
    const float* __restrict__ Wlin, const float* __restrict__ blin,
    float* __restrict__ out)
{
    constexpr int K = 384, LDS = 392;
    extern __shared__ __align__(16) char smraw[];
    __half* Xs = (__half*)smraw;            // [128][392]
    __half* Ws = Xs + 128 * LDS;            // [64][392]
    float*  bs = (float*)(Ws + 64 * LDS);   // [64]

    int t = threadIdx.x;
    int row0 = blockIdx.x * 128;

    for (int s = t; s < 128 * 48; s += 256) {
        int r = s / 48;
        int q = s - r * 48;
        int row = row0 + r;
        uint4 v = make_uint4(0u, 0u, 0u, 0u);
        if (row < NN) {
            const __half* srcp = (q < 16) ? g_h1 : (q < 32) ? g_h2 : g_h3;
            int qq = q & 15;
            v = *reinterpret_cast<const uint4*>(srcp + (size_t)row * HID + qq * 8);
        }
        *reinterpret_cast<uint4*>(Xs + r * LDS + q * 8) = v;
    }
    for (int s = t; s < 64 * 96; s += 256) {
        int c = s / 96;
        int k4 = s - c * 96;
        float4 w = make_float4(0.f, 0.f, 0.f, 0.f);
        if (c < CLS) w = *reinterpret_cast<const float4*>(Wlin + (size_t)c * K + 4 * k4);
        __half2 w0 = __floats2half2_rn(w.x, w.y), w1 = __floats2half2_rn(w.z, w.w);
        *reinterpret_cast<uint2*>(Ws + c * LDS + 4 * k4) = make_uint2(*(uint*)&w0, *(uint*)&w1);
    }
    if (t < 64) bs[t] = (t < CLS) ? blin[t] : 0.f;
    __syncthreads();

    int lane = t & 31;
    int wid = t >> 5;
    int m = wid * 16;
    int g = lane >> 2;
    int tg = lane & 3;

    uint32_t a_row = m + (lane & 15);
    uint32_t a_col = (lane >> 4) * 8;
    uint32_t adA = smem_u32(Xs + a_row * LDS + a_col);
    uint32_t b_row = (lane & 7) + ((lane >> 4) << 3);
    uint32_t b_col = ((lane >> 3) & 1) * 8;
    uint32_t adW[4];
#pragma unroll
    for (int j = 0; j < 4; j++)
        adW[j] = smem_u32(Ws + (j * 16 + b_row) * LDS + b_col);

    float acc[8][4];
#pragma unroll
    for (int nt = 0; nt < 8; nt++)
#pragma unroll
        for (int q = 0; q < 4; q++) acc[nt][q] = 0.f;

#pragma unroll 4
    for (int kk = 0; kk < 24; kk++) {
        uint32_t ko = kk * 32;
        uint a[4];
        ldsm4(a, adA + ko);
#pragma unroll
        for (int j = 0; j < 4; j++) {
            uint w[4];
            ldsm4(w, adW[j] + ko);
            mma16816(acc[2 * j],     a, w[0], w[1]);
            mma16816(acc[2 * j + 1], a, w[2], w[3]);
        }
    }

#pragma unroll
    for (int half = 0; half < 2; half++) {
        int row = row0 + m + g + half * 8;
        float v[8][2];
        float mx = -1e30f;
#pragma unroll
        for (int nt = 0; nt < 8; nt++) {
            int c = nt * 8 + tg * 2;
            float a0 = acc[nt][half * 2 + 0] + bs[c];
            float a1 = acc[nt][half * 2 + 1] + bs[c + 1];
            v[nt][0] = a0; v[nt][1] = a1;
            if (c < CLS) mx = fmaxf(mx, a0);
            if (c + 1 < CLS) mx = fmaxf(mx, a1);
        }
        mx = fmaxf(mx, __shfl_xor_sync(0xffffffffu, mx, 1));
        mx = fmaxf(mx, __shfl_xor_sync(0xffffffffu, mx, 2));
        float se = 0.f;
#pragma unroll
        for (int nt = 0; nt < 8; nt++) {
            int c = nt * 8 + tg * 2;
            if (c < CLS) se += expf(v[nt][0] - mx);
            if (c + 1 < CLS) se += expf(v[nt][1] - mx);
        }
        se += __shfl_xor_sync(0xffffffffu, se, 1);
        se += __shfl_xor_sync(0xffffffffu, se, 2);
        float lse = mx + logf(se);
        if (row < NN) {
#pragma unroll
            for (int nt = 0; nt < 8; nt++) {
                int c = nt * 8 + tg * 2;
                if (c < CLS) out[(size_t)row * CLS + c] = v[nt][0] - lse;
                if (c + 1 < CLS) out[(size_t)row * CLS + c + 1] = v[nt][1] - lse;
            }
        }
    }
}

// ---------------- launch ----------------
extern "C" void kernel_launch(void* const* d_in, const int* in_sizes, int n_in,
                              void* d_out, int out_size)
{
    const float* x0    = (const float*)d_in[0];
    const int*   ei    = (const int*)  d_in[1];
    const float* ew    = (const float*)d_in[2];
    const float* W1rel = (const float*)d_in[3];
    const float* W1rt  = (const float*)d_in[4];
    const float* b1    = (const float*)d_in[5];
    const float* W2rel = (const float*)d_in[6];
    const float* W2rt  = (const float*)d_in[7];
    const float* b2    = (const float*)d_in[8];
    const float* W3rel = (const float*)d_in[9];
    const float* W3rt  = (const float*)d_in[10];
    const float* b3    = (const float*)d_in[11];
    const float* Wlin  = (const float*)d_in[12];
    const float* blin  = (const float*)d_in[13];
    float* out = (float*)d_out;

    const int* src = ei;
    const int* dst = ei + EE;

    int* degp;
    __half *x0hp, *agghp, *h1p, *h2p, *h3p, *whp;
    cudaGetSymbolAddress((void**)&degp,  g_deg);
    cudaGetSymbolAddress((void**)&x0hp,  g_x0h);
    cudaGetSymbolAddress((void**)&agghp, g_aggh);
    cudaGetSymbolAddress((void**)&h1p,   g_h1);
    cudaGetSymbolAddress((void**)&h2p,   g_h2);
    cudaGetSymbolAddress((void**)&h3p,   g_h3);
    cudaGetSymbolAddress((void**)&whp,   g_wh);

    const int smemG = 4 * 128 * 136 * 2 + 128 * 4 + 256;           // ~140 KB
    const int smemH = 128 * 392 * 2 + 64 * 392 * 2 + 64 * 4 + 256; // ~151 KB
    cudaFuncSetAttribute(k_gemm_mma, cudaFuncAttributeMaxDynamicSharedMemorySize, smemG);
    cudaFuncSetAttribute(k_head_mma, cudaFuncAttributeMaxDynamicSharedMemorySize, smemH);

    cudaMemsetAsync(degp, 0, NN * sizeof(int));

    const int aggBlocks = NN * 32 / 256;        // 12500
    const int gemmBlocks = (NN + 127) / 128;    // 782

    // kernel launches (profiled kernel = #4 -> k_agg_h<25>)
    k_pre<<<NB_CNT + NB_CVT + NB_W, 512>>>(dst, x0, W1rel, W1rt, W2rel, W2rt, W3rel, W3rt); // 1
    k_scanA<<<(NN + 1023) / 1024, 1024>>>();                                                // 2
    k_fill<<<(EE + 511) / 512, 512>>>(src, dst, ew);                                        // 3

    // layer 1
    k_agg_h<25><<<aggBlocks, 256>>>(x0hp, agghp);                                           // 4
    k_gemm_mma<<<gemmBlocks, 256, smemG>>>(agghp, x0hp, whp, whp + 16384, b1, h1p);
    // layer 2
    k_agg_h<32><<<aggBlocks, 256>>>(h1p, agghp);
    k_gemm_mma<<<gemmBlocks, 256, smemG>>>(agghp, h1p, whp + 2 * 16384, whp + 3 * 16384, b2, h2p);
    // layer 3
    k_agg_h<32><<<aggBlocks, 256>>>(h2p, agghp);
    k_gemm_mma<<<gemmBlocks, 256, smemG>>>(agghp, h2p, whp + 4 * 16384, whp + 5 * 16384, b3, h3p);
    // head
    k_head_mma<<<gemmBlocks, 256, smemH>>>(Wlin, blin, out);
}